// round 4
// baseline (speedup 1.0000x reference)
#include <cuda_runtime.h>
#include <math.h>

#define NN    2048
#define DIN   256
#define DPROJ 256
// proj row layout: [Q 0:64 | K 64:128 | V 128:192 | R 192:256]
#define OFF_Q 0
#define OFF_K 64
#define OFF_V 128
#define OFF_R 192
#define SCALE 0.08838834764831845f   // 1/sqrt(64+64)

__device__ float g_proj[NN * DPROJ];   // 2 MB scratch

// ---------------------------------------------------------------------------
// Kernel 1: proj = H @ W^T   (2048x256 @ 256x256^T)
// ---------------------------------------------------------------------------
#define BM 64
#define BN 64
#define BK 32

__global__ __launch_bounds__(256)
void proj_kernel(const float* __restrict__ H, const float* __restrict__ W) {
    __shared__ float sA[BK][BM + 1];
    __shared__ float sB[BK][BN + 1];

    const int m0 = blockIdx.y * BM;
    const int n0 = blockIdx.x * BN;
    const int t  = threadIdx.x;
    const int tx = t & 15;        // 16 threads along n
    const int ty = t >> 4;        // 16 threads along m

    float acc[4][4];
#pragma unroll
    for (int a = 0; a < 4; ++a)
#pragma unroll
        for (int b = 0; b < 4; ++b) acc[a][b] = 0.f;

    for (int k0 = 0; k0 < DIN; k0 += BK) {
#pragma unroll
        for (int idx = t; idx < BM * BK; idx += 256) {
            int m = idx >> 5, k = idx & 31;
            sA[k][m] = H[(m0 + m) * DIN + k0 + k];
        }
#pragma unroll
        for (int idx = t; idx < BN * BK; idx += 256) {
            int n = idx >> 5, k = idx & 31;
            sB[k][n] = W[(n0 + n) * DIN + k0 + k];
        }
        __syncthreads();

#pragma unroll
        for (int k = 0; k < BK; ++k) {
            float a[4], b[4];
#pragma unroll
            for (int u = 0; u < 4; ++u) a[u] = sA[k][ty * 4 + u];
#pragma unroll
            for (int v = 0; v < 4; ++v) b[v] = sB[k][tx * 4 + v];
#pragma unroll
            for (int u = 0; u < 4; ++u)
#pragma unroll
                for (int v = 0; v < 4; ++v)
                    acc[u][v] += a[u] * b[v];
        }
        __syncthreads();
    }

#pragma unroll
    for (int u = 0; u < 4; ++u)
#pragma unroll
        for (int v = 0; v < 4; ++v)
            g_proj[(m0 + ty * 4 + u) * DPROJ + n0 + tx * 4 + v] = acc[u][v];
}

// ---------------------------------------------------------------------------
// Kernel 2: fused  s = scale*(Q K^T + R.D) ; softmax ; out = attn @ V
// One CTA handles TILE_I=8 query rows. 256 threads = 8 warps.
// ---------------------------------------------------------------------------
#define TILE_I 8
#define SST    (NN + 4)     // padded score-row stride (kills 8-way conflict)
#define JC     128          // V staging chunk (rows)

#define SMEM_FLOATS (TILE_I * SST + JC * 64)
#define SMEM_BYTES  (SMEM_FLOATS * 4)

extern __shared__ float smem[];

__global__ __launch_bounds__(256, 2)
void attn_kernel(const float* __restrict__ Dm, float* __restrict__ out) {
    float* s_s = smem;                    // [TILE_I][SST] scores
    float* s_v = smem + TILE_I * SST;     // [JC][64] V chunk

    const int tid  = threadIdx.x;
    const int warp = tid >> 5;
    const int lane = tid & 31;
    const int i0   = blockIdx.x * TILE_I;

    // Q/R pairs for this CTA's 8 rows, held in registers (lane covers dims 2l,2l+1)
    float2 q2[TILE_I], r2[TILE_I];
#pragma unroll
    for (int i = 0; i < TILE_I; ++i) {
        const float* row = g_proj + (size_t)(i0 + i) * DPROJ;
        q2[i] = *(const float2*)(row + OFF_Q + 2 * lane);
        r2[i] = *(const float2*)(row + OFF_R + 2 * lane);
    }

    // ---- Pass 1: scores.  Each warp owns a j-stripe; streams D. ----
    for (int j = warp; j < NN; j += 8) {
        const float2 k2 = *(const float2*)(g_proj + (size_t)j * DPROJ + OFF_K + 2 * lane);
        float acc[TILE_I];
#pragma unroll
        for (int i = 0; i < TILE_I; ++i) {
            const float2 d2 = *(const float2*)(Dm + ((size_t)(i0 + i) * NN + j) * 64 + 2 * lane);
            acc[i] = q2[i].x * k2.x + q2[i].y * k2.y
                   + r2[i].x * d2.x + r2[i].y * d2.y;
        }
#pragma unroll
        for (int off = 16; off > 0; off >>= 1) {
#pragma unroll
            for (int i = 0; i < TILE_I; ++i)
                acc[i] += __shfl_xor_sync(0xffffffffu, acc[i], off);
        }
#pragma unroll
        for (int i = 0; i < TILE_I; ++i)
            if (lane == i) s_s[i * SST + j] = acc[i] * SCALE;
    }
    __syncthreads();

    // ---- Pass 2: softmax, warp-per-row ----
    const int i = warp;
    float m = -INFINITY;
    for (int j = lane; j < NN; j += 32)
        m = fmaxf(m, s_s[i * SST + j]);
#pragma unroll
    for (int off = 16; off > 0; off >>= 1)
        m = fmaxf(m, __shfl_xor_sync(0xffffffffu, m, off));

    float sum = 0.f;
    for (int j = lane; j < NN; j += 32) {
        float e = __expf(s_s[i * SST + j] - m);
        s_s[i * SST + j] = e;
        sum += e;
    }
#pragma unroll
    for (int off = 16; off > 0; off >>= 1)
        sum += __shfl_xor_sync(0xffffffffu, sum, off);
    const float inv = 1.f / sum;

    // ---- Pass 3: out = attn @ V, V staged in shared per chunk ----
    float2 acc2 = make_float2(0.f, 0.f);
    for (int jb = 0; jb < NN; jb += JC) {
        __syncthreads();
        // stage V[jb : jb+JC][0:64] (V lives strided inside g_proj rows)
        for (int t4 = tid; t4 < JC * 64 / 4; t4 += 256) {
            int j = t4 >> 4;            // /16 float4s per row
            int c = (t4 & 15) << 2;     // *4
            *(float4*)(s_v + j * 64 + c) =
                *(const float4*)(g_proj + (size_t)(jb + j) * DPROJ + OFF_V + c);
        }
        __syncthreads();

        const float* srow = s_s + i * SST + jb;
#pragma unroll 4
        for (int jj = 0; jj < JC; jj += 4) {
            float4 p = *(const float4*)(srow + jj);
            float2 v0 = *(const float2*)(s_v + (jj + 0) * 64 + 2 * lane);
            float2 v1 = *(const float2*)(s_v + (jj + 1) * 64 + 2 * lane);
            float2 v2 = *(const float2*)(s_v + (jj + 2) * 64 + 2 * lane);
            float2 v3 = *(const float2*)(s_v + (jj + 3) * 64 + 2 * lane);
            acc2.x += p.x * v0.x; acc2.y += p.x * v0.y;
            acc2.x += p.y * v1.x; acc2.y += p.y * v1.y;
            acc2.x += p.z * v2.x; acc2.y += p.z * v2.y;
            acc2.x += p.w * v3.x; acc2.y += p.w * v3.y;
        }
    }

    float2 o;
    o.x = acc2.x * inv;
    o.y = acc2.y * inv;
    *(float2*)(out + (size_t)(i0 + i) * 64 + 2 * lane) = o;
}

// ---------------------------------------------------------------------------
extern "C" void kernel_launch(void* const* d_in, const int* in_sizes, int n_in,
                              void* d_out, int out_size) {
    const float* H  = (const float*)d_in[0];   // (2048, 256)
    const float* Dm = (const float*)d_in[1];   // (2048, 2048, 64)
    const float* W  = (const float*)d_in[2];   // (256, 256)
    float* out = (float*)d_out;                // (2048, 64)

    dim3 g1(DPROJ / BN, NN / BM);              // (4, 32)
    proj_kernel<<<g1, 256>>>(H, W);

    cudaFuncSetAttribute(attn_kernel,
                         cudaFuncAttributeMaxDynamicSharedMemorySize, SMEM_BYTES);
    attn_kernel<<<NN / TILE_I, 256, SMEM_BYTES>>>(Dm, out);
}

// round 5
// speedup vs baseline: 1.1000x; 1.1000x over previous
#include <cuda_runtime.h>
#include <math.h>

#define NN    2048
#define DIN   256
#define DPROJ 256
// proj row layout: [Q 0:64 | K 64:128 | V 128:192 | R 192:256]
#define OFF_Q 0
#define OFF_K 64
#define OFF_V 128
#define OFF_R 192
#define SCALE 0.08838834764831845f   // 1/sqrt(64+64)

__device__ float g_proj[NN * DPROJ];        // 2 MB
__device__ float g_S[(size_t)NN * NN];      // 16 MB score matrix

// ---------------------------------------------------------------------------
// Kernel 1: proj = H @ W^T   (2048x256 @ 256x256^T)
// ---------------------------------------------------------------------------
#define BM 64
#define BN 64
#define BK 32

__global__ __launch_bounds__(256)
void proj_kernel(const float* __restrict__ H, const float* __restrict__ W) {
    __shared__ float sA[BK][BM + 1];
    __shared__ float sB[BK][BN + 1];

    const int m0 = blockIdx.y * BM;
    const int n0 = blockIdx.x * BN;
    const int t  = threadIdx.x;
    const int tx = t & 15;
    const int ty = t >> 4;

    float acc[4][4];
#pragma unroll
    for (int a = 0; a < 4; ++a)
#pragma unroll
        for (int b = 0; b < 4; ++b) acc[a][b] = 0.f;

    for (int k0 = 0; k0 < DIN; k0 += BK) {
#pragma unroll
        for (int idx = t; idx < BM * BK; idx += 256) {
            int m = idx >> 5, k = idx & 31;
            sA[k][m] = H[(m0 + m) * DIN + k0 + k];
        }
#pragma unroll
        for (int idx = t; idx < BN * BK; idx += 256) {
            int n = idx >> 5, k = idx & 31;
            sB[k][n] = W[(n0 + n) * DIN + k0 + k];
        }
        __syncthreads();

#pragma unroll
        for (int k = 0; k < BK; ++k) {
            float a[4], b[4];
#pragma unroll
            for (int u = 0; u < 4; ++u) a[u] = sA[k][ty * 4 + u];
#pragma unroll
            for (int v = 0; v < 4; ++v) b[v] = sB[k][tx * 4 + v];
#pragma unroll
            for (int u = 0; u < 4; ++u)
#pragma unroll
                for (int v = 0; v < 4; ++v)
                    acc[u][v] += a[u] * b[v];
        }
        __syncthreads();
    }

#pragma unroll
    for (int u = 0; u < 4; ++u)
#pragma unroll
        for (int v = 0; v < 4; ++v)
            g_proj[(m0 + ty * 4 + u) * DPROJ + n0 + tx * 4 + v] = acc[u][v];
}

// ---------------------------------------------------------------------------
// Kernel 2: S[i][j] = scale * (Q[i].K[j] + R[i].D[i,j])
// Grid: (NN/TJ, NN/TI) = (8, 256) = 2048 CTAs, 256 threads (8 warps).
// Each warp streams 32 consecutive j rows of D for 8 i's — fully coalesced.
// ---------------------------------------------------------------------------
#define TI 8
#define TJ 256

__global__ __launch_bounds__(256, 3)
void score_kernel(const float* __restrict__ Dm) {
    const int tid  = threadIdx.x;
    const int warp = tid >> 5;
    const int lane = tid & 31;
    const int i0   = blockIdx.y * TI;
    const int jw0  = blockIdx.x * TJ + warp * 32;   // warp's 32-j stripe

    // Q/R register tiles: lane holds dims (2*lane, 2*lane+1)
    float2 q2[TI], r2[TI];
#pragma unroll
    for (int i = 0; i < TI; ++i) {
        const float* row = g_proj + (size_t)(i0 + i) * DPROJ;
        q2[i] = *(const float2*)(row + OFF_Q + 2 * lane);
        r2[i] = *(const float2*)(row + OFF_R + 2 * lane);
    }

#pragma unroll 2
    for (int t = 0; t < 32; ++t) {
        const int j = jw0 + t;
        const float2 k2 = *(const float2*)(g_proj + (size_t)j * DPROJ + OFF_K + 2 * lane);
        float acc[TI];
#pragma unroll
        for (int i = 0; i < TI; ++i) {
            const float2 d2 = *(const float2*)(Dm + ((size_t)(i0 + i) * NN + j) * 64 + 2 * lane);
            acc[i] = q2[i].x * k2.x + q2[i].y * k2.y
                   + r2[i].x * d2.x + r2[i].y * d2.y;
        }
#pragma unroll
        for (int off = 16; off > 0; off >>= 1) {
#pragma unroll
            for (int i = 0; i < TI; ++i)
                acc[i] += __shfl_xor_sync(0xffffffffu, acc[i], off);
        }
#pragma unroll
        for (int i = 0; i < TI; ++i)
            if (lane == i) g_S[(size_t)(i0 + i) * NN + j] = acc[i] * SCALE;
    }
}

// ---------------------------------------------------------------------------
// Kernel 3: row softmax + attn @ V.
// 512 CTAs x 128 threads; 4 warps = 4 rows per CTA; V staged in 16 KB chunks.
// ---------------------------------------------------------------------------
#define RI 4            // rows per CTA
#define JC 64           // V chunk rows

__global__ __launch_bounds__(128)
void pv_kernel(float* __restrict__ out) {
    __shared__ float s_v[JC * 64];   // 16 KB V chunk

    const int tid  = threadIdx.x;
    const int warp = tid >> 5;
    const int lane = tid & 31;
    const int row  = blockIdx.x * RI + warp;

    const float* srow = g_S + (size_t)row * NN;

    // Phase 1: row max (coalesced float4 stream)
    float m = -INFINITY;
    for (int j4 = lane; j4 < NN / 4; j4 += 32) {
        float4 s = ((const float4*)srow)[j4];
        m = fmaxf(m, fmaxf(fmaxf(s.x, s.y), fmaxf(s.z, s.w)));
    }
#pragma unroll
    for (int off = 16; off > 0; off >>= 1)
        m = fmaxf(m, __shfl_xor_sync(0xffffffffu, m, off));

    // Phase 2: stream exp + PV with V staged in shared
    float2 acc = make_float2(0.f, 0.f);
    float  sum = 0.f;

    for (int jb = 0; jb < NN; jb += JC) {
        __syncthreads();
        // stage V[jb : jb+JC][0:64]  (V is strided inside g_proj rows)
        for (int t4 = tid; t4 < JC * 64 / 4; t4 += 128) {
            int j = t4 >> 4;
            int c = (t4 & 15) << 2;
            *(float4*)(s_v + j * 64 + c) =
                *(const float4*)(g_proj + (size_t)(jb + j) * DPROJ + OFF_V + c);
        }
        __syncthreads();

        float p0 = __expf(srow[jb + lane]      - m);
        float p1 = __expf(srow[jb + 32 + lane] - m);
        sum += p0 + p1;

#pragma unroll
        for (int jj = 0; jj < 32; ++jj) {
            float pa = __shfl_sync(0xffffffffu, p0, jj);
            float pb = __shfl_sync(0xffffffffu, p1, jj);
            float2 va = *(const float2*)(s_v + jj * 64 + 2 * lane);
            float2 vb = *(const float2*)(s_v + (32 + jj) * 64 + 2 * lane);
            acc.x += pa * va.x; acc.y += pa * va.y;
            acc.x += pb * vb.x; acc.y += pb * vb.y;
        }
    }

#pragma unroll
    for (int off = 16; off > 0; off >>= 1)
        sum += __shfl_xor_sync(0xffffffffu, sum, off);
    const float inv = 1.f / sum;

    float2 o;
    o.x = acc.x * inv;
    o.y = acc.y * inv;
    *(float2*)(out + (size_t)row * 64 + 2 * lane) = o;
}

// ---------------------------------------------------------------------------
extern "C" void kernel_launch(void* const* d_in, const int* in_sizes, int n_in,
                              void* d_out, int out_size) {
    const float* H  = (const float*)d_in[0];   // (2048, 256)
    const float* Dm = (const float*)d_in[1];   // (2048, 2048, 64)
    const float* W  = (const float*)d_in[2];   // (256, 256)
    float* out = (float*)d_out;                // (2048, 64)

    dim3 g1(DPROJ / BN, NN / BM);              // (4, 32)
    proj_kernel<<<g1, 256>>>(H, W);

    dim3 g2(NN / TJ, NN / TI);                 // (8, 256)
    score_kernel<<<g2, 256>>>(Dm);

    pv_kernel<<<NN / RI, 128>>>(out);
}